// round 2
// baseline (speedup 1.0000x reference)
#include <cuda_runtime.h>
#include <cuda_bf16.h>

#define N_NODES 50000
#define N_EDGES 1250000
#define HID 64
#define CDIM 128   // 2*HID

// ---------------------------------------------------------------------------
// Scratch (device globals — no allocation allowed)
// ---------------------------------------------------------------------------
__device__ int d_counts[N_NODES];
__device__ int d_offsets[N_NODES + 1];
__device__ int d_cursor[N_NODES];
__device__ int d_edge_sorted[N_EDGES];

// ---------------------------------------------------------------------------
// K0: zero the histogram
// ---------------------------------------------------------------------------
__global__ void zero_counts_kernel() {
    int i = blockIdx.x * blockDim.x + threadIdx.x;
    if (i < N_NODES) d_counts[i] = 0;
}

// ---------------------------------------------------------------------------
// K1: histogram of destination nodes
// ---------------------------------------------------------------------------
__global__ void hist_kernel(const int* __restrict__ row) {
    int e = blockIdx.x * blockDim.x + threadIdx.x;
    if (e < N_EDGES) atomicAdd(&d_counts[__ldg(row + e)], 1);
}

// ---------------------------------------------------------------------------
// K2: single-block exclusive scan over counts -> offsets (+ cursor copy)
// ---------------------------------------------------------------------------
#define SCAN_NT 1024
__global__ void scan_kernel() {
    __shared__ int s[SCAN_NT];
    const int C = (N_NODES + SCAN_NT - 1) / SCAN_NT;   // 49
    int t = threadIdx.x;
    int start = t * C;

    int local = 0;
    for (int i = 0; i < C; i++) {
        int idx = start + i;
        if (idx < N_NODES) local += d_counts[idx];
    }
    s[t] = local;
    __syncthreads();

    // Hillis-Steele inclusive scan over 1024 partials
    for (int off = 1; off < SCAN_NT; off <<= 1) {
        int v = 0;
        if (t >= off) v = s[t - off];
        __syncthreads();
        if (t >= off) s[t] += v;
        __syncthreads();
    }
    int run = s[t] - local;   // exclusive prefix for this thread's chunk

    for (int i = 0; i < C; i++) {
        int idx = start + i;
        if (idx < N_NODES) {
            d_offsets[idx] = run;
            d_cursor[idx]  = run;
            run += d_counts[idx];
        }
    }
    if (t == SCAN_NT - 1) d_offsets[N_NODES] = run;   // == N_EDGES
}

// ---------------------------------------------------------------------------
// K3: bin edge ids by destination node
// ---------------------------------------------------------------------------
__global__ void bin_kernel(const int* __restrict__ row) {
    int e = blockIdx.x * blockDim.x + threadIdx.x;
    if (e < N_EDGES) {
        int r = __ldg(row + e);
        int pos = atomicAdd(&d_cursor[r], 1);
        d_edge_sorted[pos] = e;
    }
}

// ---------------------------------------------------------------------------
// K4: fused gather + combined-write + MLP.
// 256 threads/block = 4 groups of 64. Group owns one node per tile; thread j
// owns feature j. Gather replaces all f32 atomics: each edge_attr row (256 B)
// is read exactly once, fully coalesced.
// ---------------------------------------------------------------------------
__global__ void fused_kernel(const float* __restrict__ x,
                             const float* __restrict__ edge_attr,
                             const float* __restrict__ W1,
                             const float* __restrict__ b1,
                             const float* __restrict__ W2,
                             const float* __restrict__ b2,
                             float* __restrict__ out,
                             float* __restrict__ combined) {
    extern __shared__ float smem[];
    float* sW1 = smem;                    // 128*64
    float* sW2 = sW1 + CDIM * HID;        // 64*64
    float* sb1 = sW2 + HID * HID;         // 64
    float* sb2 = sb1 + HID;               // 64
    float* sc  = sb2 + HID;               // 4*128
    float* sh  = sc + 4 * CDIM;           // 4*64

    int tid = threadIdx.x;

    for (int i = tid; i < CDIM * HID; i += blockDim.x) sW1[i] = W1[i];
    for (int i = tid; i < HID * HID;  i += blockDim.x) sW2[i] = W2[i];
    if (tid < HID) { sb1[tid] = b1[tid]; sb2[tid] = b2[tid]; }
    __syncthreads();

    int g = tid >> 6;          // group 0..3
    int j = tid & 63;          // feature

    int n_tiles = (N_NODES + 3) / 4;
    for (int tile = blockIdx.x; tile < n_tiles; tile += gridDim.x) {
        int node = tile * 4 + g;
        bool active = node < N_NODES;

        float xv = 0.f, agg = 0.f;
        if (active) {
            xv = __ldg(x + (size_t)node * HID + j);
            int beg = d_offsets[node];
            int end = d_offsets[node + 1];
            int p = beg;
            // 4-way pipelined gather: batch edge-id loads, then attr loads
            for (; p + 4 <= end; p += 4) {
                int e0 = d_edge_sorted[p + 0];
                int e1 = d_edge_sorted[p + 1];
                int e2 = d_edge_sorted[p + 2];
                int e3 = d_edge_sorted[p + 3];
                float v0 = __ldg(edge_attr + (size_t)e0 * HID + j);
                float v1 = __ldg(edge_attr + (size_t)e1 * HID + j);
                float v2 = __ldg(edge_attr + (size_t)e2 * HID + j);
                float v3 = __ldg(edge_attr + (size_t)e3 * HID + j);
                agg += (v0 + v1) + (v2 + v3);
            }
            for (; p < end; p++) {
                int e = d_edge_sorted[p];
                agg += __ldg(edge_attr + (size_t)e * HID + j);
            }
            // combined output row
            combined[(size_t)node * CDIM + j]       = xv;
            combined[(size_t)node * CDIM + HID + j] = agg;
        }
        sc[g * CDIM + j]       = xv;
        sc[g * CDIM + HID + j] = agg;
        __syncthreads();

        // layer 1 + SiLU
        float acc = sb1[j];
        const float* c = sc + g * CDIM;
        #pragma unroll
        for (int i = 0; i < CDIM; i++)
            acc = fmaf(c[i], sW1[i * HID + j], acc);
        float h = acc / (1.0f + __expf(-acc));
        sh[g * HID + j] = h;
        __syncthreads();

        // layer 2
        float acc2 = sb2[j];
        const float* hh = sh + g * HID;
        #pragma unroll
        for (int k = 0; k < HID; k++)
            acc2 = fmaf(hh[k], sW2[k * HID + j], acc2);
        if (active)
            out[(size_t)node * HID + j] = acc2;
        __syncthreads();   // protect sc/sh before next tile
    }
}

// ---------------------------------------------------------------------------
extern "C" void kernel_launch(void* const* d_in, const int* in_sizes, int n_in,
                              void* d_out, int out_size) {
    const int*   edge_index = (const int*)d_in[0];   // [2, N_EDGES]; row = first half
    const float* edge_attr  = (const float*)d_in[1]; // [N_EDGES, 64]
    const float* x          = (const float*)d_in[2]; // [N_NODES, 64]
    const float* W1         = (const float*)d_in[3]; // [128, 64]
    const float* b1         = (const float*)d_in[4]; // [64]
    const float* W2         = (const float*)d_in[5]; // [64, 64]
    const float* b2         = (const float*)d_in[6]; // [64]

    float* out      = (float*)d_out;                 // [N_NODES, 64]
    float* combined = out + (size_t)N_NODES * HID;   // [N_NODES, 128]

    const int T = 256;

    zero_counts_kernel<<<(N_NODES + T - 1) / T, T>>>();
    hist_kernel<<<(N_EDGES + T - 1) / T, T>>>(edge_index);
    scan_kernel<<<1, SCAN_NT>>>();
    bin_kernel<<<(N_EDGES + T - 1) / T, T>>>(edge_index);

    int smem_bytes = (CDIM * HID + HID * HID + 2 * HID + 4 * CDIM + 4 * HID)
                     * (int)sizeof(float);
    cudaFuncSetAttribute(fused_kernel,
                         cudaFuncAttributeMaxDynamicSharedMemorySize,
                         smem_bytes);
    fused_kernel<<<592, T, smem_bytes>>>(x, edge_attr, W1, b1, W2, b2,
                                         out, combined);
}

// round 3
// speedup vs baseline: 2.4002x; 2.4002x over previous
#include <cuda_runtime.h>
#include <cuda_bf16.h>

#define N_NODES 50000
#define N_EDGES 1250000
#define HID 64
#define CDIM 128
#define NTILE 32                                     // nodes per block-tile
#define N_TILES ((N_NODES + NTILE - 1) / NTILE)      // 1563
#define SCAT_BLOCKS 444
#define GEMM_BLOCKS 148
#define TOTAL_BLOCKS (SCAT_BLOCKS + GEMM_BLOCKS)
#define TOTAL_ITEMS (16LL * N_EDGES)                 // 20M (edge, float4-group) items
#define SPLIT_ITEMS 17500000LL                       // pool split scatter vs helper

// scratch: t1 = x @ W1[0:64] + b1
__device__ float d_t1[(size_t)N_NODES * HID];

// ---------------------------------------------------------------------------
// K0: zero combined[:, 64:128] (the scatter-add target)
// ---------------------------------------------------------------------------
__global__ void zero_agg_kernel(float4* __restrict__ comb4) {
    int i = blockIdx.x * blockDim.x + threadIdx.x;   // over N_NODES*16
    if (i < N_NODES * 16) {
        int n = i >> 4, q = i & 15;
        comb4[(size_t)n * 32 + 16 + q] = make_float4(0.f, 0.f, 0.f, 0.f);
    }
}

// ---------------------------------------------------------------------------
// scatter work: sequential edge_attr stream + vector reductions into L2
// ---------------------------------------------------------------------------
__device__ __forceinline__ void scatter_range(const int* __restrict__ row,
                                              const float4* __restrict__ attr4,
                                              float* __restrict__ combined,
                                              long long beg, long long end,
                                              long long idx0, long long stride) {
    for (long long idx = beg + idx0; idx < end; idx += stride) {
        int e = (int)(idx >> 4);
        int g = (int)(idx & 15);
        int r = __ldg(row + e);
        float4 v = __ldg(attr4 + idx);
        float* dst = combined + (size_t)r * CDIM + HID + g * 4;
        asm volatile("red.global.add.v4.f32 [%0], {%1, %2, %3, %4};"
                     :: "l"(dst), "f"(v.x), "f"(v.y), "f"(v.z), "f"(v.w)
                     : "memory");
    }
}

// ---------------------------------------------------------------------------
// K1: fused scatter + t1-GEMM (+ combined[:,0:64] = x copy).
// Blocks [0, SCAT_BLOCKS) scatter; blocks [SCAT_BLOCKS, TOTAL) do the
// x @ W1a GEMM on the fma pipe (overlapping the scatter's LSU/REDG work),
// then help finish the scatter tail.
// ---------------------------------------------------------------------------
__global__ void scatter_gemm_kernel(const int* __restrict__ row,
                                    const float4* __restrict__ attr4,
                                    const float4* __restrict__ x4,
                                    const float* __restrict__ W1,
                                    const float* __restrict__ b1,
                                    float* __restrict__ combined) {
    int tid = threadIdx.x;

    if (blockIdx.x < SCAT_BLOCKS) {
        long long idx0 = (long long)blockIdx.x * 256 + tid;
        scatter_range(row, attr4, combined, 0, SPLIT_ITEMS,
                      idx0, (long long)SCAT_BLOCKS * 256);
        return;
    }

    // ---- GEMM branch: t1 = x @ W1[0:64,:] + b1 ----
    extern __shared__ float4 smem4[];
    float*  sW  = (float*)smem4;                 // 64*64 floats (16 KB)
    float4* sx4 = smem4 + (HID * HID) / 4;       // 32 nodes * 16 float4 (8 KB)

    for (int i = tid; i < HID * HID; i += 256) sW[i] = W1[i];
    float bj = __ldg(b1 + (tid & 63));
    __syncthreads();

    int g = tid >> 6;          // group 0..3
    int j = tid & 63;          // output feature
    int bid = blockIdx.x - SCAT_BLOCKS;
    float4* comb4 = (float4*)combined;

    for (int tile = bid; tile < N_TILES; tile += GEMM_BLOCKS) {
        int node0 = tile * NTILE;

        // stage x rows into smem; also emit combined[:,0:64] = x
        for (int i = tid; i < NTILE * 16; i += 256) {
            int n = node0 + (i >> 4), q = i & 15;
            float4 v = make_float4(0.f, 0.f, 0.f, 0.f);
            if (n < N_NODES) {
                v = __ldg(x4 + (size_t)n * 16 + q);
                comb4[(size_t)n * 32 + q] = v;
            }
            sx4[i] = v;
        }
        __syncthreads();

        float acc[8];
        #pragma unroll
        for (int n = 0; n < 8; n++) acc[n] = bj;

        const float4* c0 = sx4 + g * 8 * 16;
        #pragma unroll 4
        for (int i4 = 0; i4 < 16; i4++) {
            float w0 = sW[(i4 * 4 + 0) * HID + j];
            float w1 = sW[(i4 * 4 + 1) * HID + j];
            float w2 = sW[(i4 * 4 + 2) * HID + j];
            float w3 = sW[(i4 * 4 + 3) * HID + j];
            #pragma unroll
            for (int n = 0; n < 8; n++) {
                float4 c = c0[n * 16 + i4];
                acc[n] = fmaf(c.x, w0, acc[n]);
                acc[n] = fmaf(c.y, w1, acc[n]);
                acc[n] = fmaf(c.z, w2, acc[n]);
                acc[n] = fmaf(c.w, w3, acc[n]);
            }
        }
        #pragma unroll
        for (int n = 0; n < 8; n++) {
            int node = node0 + g * 8 + n;
            if (node < N_NODES) d_t1[(size_t)node * HID + j] = acc[n];
        }
        __syncthreads();
    }

    // ---- help finish the scatter tail ----
    long long idx0 = (long long)bid * 256 + tid;
    scatter_range(row, attr4, combined, SPLIT_ITEMS, TOTAL_ITEMS,
                  idx0, (long long)GEMM_BLOCKS * 256);
}

// ---------------------------------------------------------------------------
// K2: out = silu(t1 + agg @ W1[64:128,:]) @ W2 + b2
// 8-node register blocking + float4 smem loads: ~1.4 instr per FMA.
// ---------------------------------------------------------------------------
__global__ void mlp2_kernel(const float* __restrict__ combined,
                            const float* __restrict__ W1,
                            const float* __restrict__ W2,
                            const float* __restrict__ b2,
                            float* __restrict__ out) {
    extern __shared__ float4 smem4[];
    float*  sW1b  = (float*)smem4;                     // 64*64 (16 KB)
    float*  sW2   = sW1b + HID * HID;                  // 64*64 (16 KB)
    float4* sagg4 = (float4*)(sW2 + HID * HID);        // 32*16 float4 (8 KB)
    float4* sh4   = sagg4 + NTILE * 16;                // 32*16 float4 (8 KB)
    float*  sh    = (float*)sh4;

    int tid = threadIdx.x;
    for (int i = tid; i < HID * HID; i += 256) sW1b[i] = W1[HID * HID + i];
    for (int i = tid; i < HID * HID; i += 256) sW2[i]  = W2[i];
    float b2j = __ldg(b2 + (tid & 63));
    __syncthreads();

    int g = tid >> 6;
    int j = tid & 63;
    const float4* comb4 = (const float4*)combined;

    for (int tile = blockIdx.x; tile < N_TILES; tile += gridDim.x) {
        int node0 = tile * NTILE;

        // stage agg rows
        for (int i = tid; i < NTILE * 16; i += 256) {
            int n = node0 + (i >> 4), q = i & 15;
            sagg4[i] = (n < N_NODES)
                         ? __ldg(comb4 + (size_t)n * 32 + 16 + q)
                         : make_float4(0.f, 0.f, 0.f, 0.f);
        }
        __syncthreads();

        // layer 1b: acc = t1 + agg @ W1b
        float acc[8];
        #pragma unroll
        for (int n = 0; n < 8; n++) {
            int node = node0 + g * 8 + n;
            acc[n] = (node < N_NODES) ? d_t1[(size_t)node * HID + j] : 0.f;
        }
        const float4* c0 = sagg4 + g * 8 * 16;
        #pragma unroll 4
        for (int k4 = 0; k4 < 16; k4++) {
            float w0 = sW1b[(k4 * 4 + 0) * HID + j];
            float w1 = sW1b[(k4 * 4 + 1) * HID + j];
            float w2 = sW1b[(k4 * 4 + 2) * HID + j];
            float w3 = sW1b[(k4 * 4 + 3) * HID + j];
            #pragma unroll
            for (int n = 0; n < 8; n++) {
                float4 c = c0[n * 16 + k4];
                acc[n] = fmaf(c.x, w0, acc[n]);
                acc[n] = fmaf(c.y, w1, acc[n]);
                acc[n] = fmaf(c.z, w2, acc[n]);
                acc[n] = fmaf(c.w, w3, acc[n]);
            }
        }
        // SiLU -> smem
        #pragma unroll
        for (int n = 0; n < 8; n++) {
            float a = acc[n];
            sh[(g * 8 + n) * HID + j] = a / (1.0f + __expf(-a));
        }
        __syncthreads();

        // layer 2
        float acc2[8];
        #pragma unroll
        for (int n = 0; n < 8; n++) acc2[n] = b2j;
        const float4* h0 = sh4 + g * 8 * 16;
        #pragma unroll 4
        for (int k4 = 0; k4 < 16; k4++) {
            float w0 = sW2[(k4 * 4 + 0) * HID + j];
            float w1 = sW2[(k4 * 4 + 1) * HID + j];
            float w2 = sW2[(k4 * 4 + 2) * HID + j];
            float w3 = sW2[(k4 * 4 + 3) * HID + j];
            #pragma unroll
            for (int n = 0; n < 8; n++) {
                float4 c = h0[n * 16 + k4];
                acc2[n] = fmaf(c.x, w0, acc2[n]);
                acc2[n] = fmaf(c.y, w1, acc2[n]);
                acc2[n] = fmaf(c.z, w2, acc2[n]);
                acc2[n] = fmaf(c.w, w3, acc2[n]);
            }
        }
        #pragma unroll
        for (int n = 0; n < 8; n++) {
            int node = node0 + g * 8 + n;
            if (node < N_NODES) out[(size_t)node * HID + j] = acc2[n];
        }
        __syncthreads();
    }
}

// ---------------------------------------------------------------------------
extern "C" void kernel_launch(void* const* d_in, const int* in_sizes, int n_in,
                              void* d_out, int out_size) {
    const int*   edge_index = (const int*)d_in[0];   // [2, N_EDGES]; row = first half
    const float* edge_attr  = (const float*)d_in[1]; // [N_EDGES, 64]
    const float* x          = (const float*)d_in[2]; // [N_NODES, 64]
    const float* W1         = (const float*)d_in[3]; // [128, 64]
    const float* b1         = (const float*)d_in[4]; // [64]
    const float* W2         = (const float*)d_in[5]; // [64, 64]
    const float* b2         = (const float*)d_in[6]; // [64]

    float* out      = (float*)d_out;                 // [N_NODES, 64]
    float* combined = out + (size_t)N_NODES * HID;   // [N_NODES, 128]

    // K0: zero agg half
    {
        int total = N_NODES * 16;
        zero_agg_kernel<<<(total + 255) / 256, 256>>>((float4*)combined);
    }

    // K1: scatter + t1 GEMM + x copy
    {
        int smem = (HID * HID) * 4 + NTILE * 16 * 16;   // 16 KB + 8 KB
        cudaFuncSetAttribute(scatter_gemm_kernel,
                             cudaFuncAttributeMaxDynamicSharedMemorySize, smem);
        scatter_gemm_kernel<<<TOTAL_BLOCKS, 256, smem>>>(
            edge_index, (const float4*)edge_attr, (const float4*)x,
            W1, b1, combined);
    }

    // K2: remaining MLP
    {
        int smem = 2 * (HID * HID) * 4 + 2 * NTILE * 16 * 16;  // 48 KB
        cudaFuncSetAttribute(mlp2_kernel,
                             cudaFuncAttributeMaxDynamicSharedMemorySize, smem);
        mlp2_kernel<<<592, 256, smem>>>(combined, W1, W2, b2, out);
    }
}